// round 14
// baseline (speedup 1.0000x reference)
#include <cuda_runtime.h>
#include <cuda_fp16.h>
#include <cstdint>
#include <math.h>

#define T_   2048
#define HS_  4096
#define NH_  32
#define NKV_ 8
#define HD_  128
#define QKVN_ ((NH_ + 2*NKV_)*HD_)   // 6144

// ======================= helpers ===========================================
__device__ __forceinline__ uint32_t smem_to_u32(const void* smem_ptr) {
    uint32_t addr;
    asm("{ .reg .u64 tmp; cvta.to.shared.u64 tmp, %1; cvt.u32.u64 %0, tmp; }"
        : "=r"(addr) : "l"(smem_ptr));
    return addr;
}
__device__ __forceinline__ void ldsm_x4(uint32_t addr, uint32_t* r) {
    asm volatile("ldmatrix.sync.aligned.m8n8.x4.shared.b16 {%0,%1,%2,%3}, [%4];"
        : "=r"(r[0]), "=r"(r[1]), "=r"(r[2]), "=r"(r[3]) : "r"(addr));
}
__device__ __forceinline__ void ldsm_x4_trans(uint32_t addr, uint32_t* r) {
    asm volatile("ldmatrix.sync.aligned.m8n8.x4.trans.shared.b16 {%0,%1,%2,%3}, [%4];"
        : "=r"(r[0]), "=r"(r[1]), "=r"(r[2]), "=r"(r[3]) : "r"(addr));
}
__device__ __forceinline__ void mma16816(float* d, const uint32_t* a,
                                         const uint32_t b0, const uint32_t b1) {
    asm volatile("mma.sync.aligned.m16n8k16.row.col.f32.f16.f16.f32 "
        "{%0,%1,%2,%3}, {%4,%5,%6,%7}, {%8,%9}, {%0,%1,%2,%3};"
        : "+f"(d[0]), "+f"(d[1]), "+f"(d[2]), "+f"(d[3])
        : "r"(a[0]), "r"(a[1]), "r"(a[2]), "r"(a[3]), "r"(b0), "r"(b1));
}
__device__ __forceinline__ uint32_t packh(float a, float b) {
    __half2 t = __floats2half2_rn(a, b);
    return *reinterpret_cast<uint32_t*>(&t);
}
__device__ __forceinline__ void split2h(float a, float b,
                                        uint32_t& hi, uint32_t& lo) {
    __half ha = __float2half_rn(a), hb = __float2half_rn(b);
    hi = packh(__half2float(ha), __half2float(hb));
    lo = packh(a - __half2float(ha), b - __half2float(hb));
}
__device__ __forceinline__ void cvt_f4(const float* __restrict__ src,
                                       __half* __restrict__ dst, int idx4) {
    float4 v = *(const float4*)(src + idx4 * 4);
    __half2* hp = (__half2*)(dst + idx4 * 4);
    hp[0] = __floats2half2_rn(v.x, v.y);
    hp[1] = __floats2half2_rn(v.z, v.w);
}

// ======================= scratch (device globals) ===========================
__device__ __align__(256) __half g_xn [T_*HS_];
__device__ __align__(256) __half g_wq [QKVN_*HS_];
__device__ __align__(256) __half g_wo [HS_*HS_];
__device__ __align__(256) __half g_att[T_*HS_];
__device__ float g_qkv[T_*QKVN_];
__device__ __align__(256) __half g_qh[NH_ *T_*HD_];
__device__ __align__(256) __half g_ql[NH_ *T_*HD_];
__device__ __align__(256) __half g_k [NKV_*T_*HD_];
__device__ __align__(256) __half g_v [NKV_*T_*HD_];

// ======================= kernel: RMSNorm(hidden) + qkv_w convert ============
// blocks [0, T_): rmsnorm rows. blocks [T_, T_+256): grid-stride convert.
__global__ void rmsnorm_cvt_kernel(const float* __restrict__ x,
                                   const float* __restrict__ w,
                                   const float* __restrict__ wq_src) {
    if (blockIdx.x >= T_) {
        int base = (blockIdx.x - T_) * blockDim.x + threadIdx.x;
        int n4 = QKVN_ * HS_ / 4;
        for (int i = base; i < n4; i += 256 * 256)
            cvt_f4(wq_src, g_wq, i);
        return;
    }
    int row = blockIdx.x;
    const float* xr = x + (size_t)row * HS_;
    float ss = 0.f;
    for (int i = threadIdx.x; i < HS_; i += blockDim.x) {
        float v = xr[i];
        ss += v * v;
    }
    for (int off = 16; off; off >>= 1)
        ss += __shfl_xor_sync(0xffffffffu, ss, off);
    __shared__ float wr[8];
    int lane = threadIdx.x & 31, wid = threadIdx.x >> 5;
    if (lane == 0) wr[wid] = ss;
    __syncthreads();
    float tot = 0.f;
#pragma unroll
    for (int i = 0; i < 8; i++) tot += wr[i];
    float inv = rsqrtf(tot / (float)HS_ + 1e-6f);
    for (int i = threadIdx.x; i < HS_; i += blockDim.x) {
        float v = xr[i] * inv * w[i];
        g_xn[(size_t)row * HS_ + i] = __float2half_rn(v);
    }
}

// ======================= fp16 GEMM: C = A*B^T (+bias) + optional convert ====
// 128 threads, 4 warps (2x2), CTA 128x128, warp tile 64x64,
// BK=32, 4-stage ring, top-issued prefetch, ONE sync per iter, 2 CTAs/SM.
// Blocks with blockIdx.x >= gxmain run a grid-stride fp32->fp16 convert
// (rides free on the compute-bound GEMM's idle DRAM bandwidth).
#define BM 128
#define BN 128
#define BK 32
#define ROWB 80                  // bytes per smem row: 40 fp16 (pad 32->40)
#define A_ARR (128 * ROWB)       // 10240 per array
#define B_OFF  A_ARR
#define STG  (2 * A_ARR)         // 20480 bytes per stage
#define NSTAGE 4
#define GEMM_SMEM (NSTAGE * STG) // 81920 -> 2 CTAs/SM

__device__ __forceinline__ void gemm_load_stage(
    uint32_t sb, int stage,
    const __half* __restrict__ A, const __half* __restrict__ B,
    int bm, int bn, int k0, int K, int tid)
{
    uint32_t base = sb + stage * STG;
#pragma unroll
    for (int ii = 0; ii < 8; ii++) {
        int s = tid + ii * 128;
        int arr = s >> 9;                // 0=A 1=B
        int r = (s >> 2) & 127, c = s & 3;
        const __half* srcb = arr ? B : A;
        int grow = (arr ? bn : bm) + r;
        const __half* src = srcb + (size_t)grow * K + k0 + c * 8;
        uint32_t dst = base + arr * A_ARR + r * ROWB + c * 16;
        asm volatile("cp.async.cg.shared.global [%0], [%1], 16;"
                     :: "r"(dst), "l"(src));
    }
    asm volatile("cp.async.commit_group;" ::: "memory");
}

__global__ void __launch_bounds__(128, 2)
gemm_fp16_kernel(const __half* __restrict__ A,
                 const __half* __restrict__ B,
                 const float* __restrict__ bias,
                 float* __restrict__ C, int N, int K, int gxmain,
                 const float* __restrict__ csrc,
                 __half* __restrict__ cdst, int cn)
{
    if (blockIdx.x >= gxmain) {
        // conversion rider blocks
        int cblk = (blockIdx.x - gxmain) + 8 * blockIdx.y;   // 0..127
        int base = cblk * 128 + threadIdx.x;                 // 16384 threads
        int n4 = cn / 4;
        for (int i = base; i < n4; i += 128 * 128)
            cvt_f4(csrc, cdst, i);
        return;
    }

    extern __shared__ char smem[];
    uint32_t sb = smem_to_u32(smem);
    int tid = threadIdx.x, lane = tid & 31, wid = tid >> 5;
    int wm = wid >> 1, wn = wid & 1;       // warp grid 2 x 2
    int bm = blockIdx.y * BM, bn = blockIdx.x * BN;
    int nk = K / BK;

    float acc[4][8][4];
#pragma unroll
    for (int i = 0; i < 4; i++)
#pragma unroll
        for (int j = 0; j < 8; j++)
#pragma unroll
            for (int c = 0; c < 4; c++) acc[i][j][c] = 0.f;

    gemm_load_stage(sb, 0, A, B, bm, bn, 0,      K, tid);
    gemm_load_stage(sb, 1, A, B, bm, bn, BK,     K, tid);
    gemm_load_stage(sb, 2, A, B, bm, bn, 2 * BK, K, tid);
    gemm_load_stage(sb, 3, A, B, bm, bn, 3 * BK, K, tid);

    int a_r = (lane & 15);
    int a_c8 = (lane >> 4) << 3;
    int b_r = (lane & 7) + ((lane & 16) >> 1);
    int b_c8 = (lane & 8);

    for (int it = 0; it < nk; it++) {
        asm volatile("cp.async.wait_group 2;" ::: "memory");
        __syncthreads();

        if (it >= 1) {
            if (it + 3 < nk)
                gemm_load_stage(sb, (it + 3) % NSTAGE, A, B, bm, bn,
                                (it + 3) * BK, K, tid);
            else
                asm volatile("cp.async.commit_group;" ::: "memory");
        }

        uint32_t base = sb + (it % NSTAGE) * STG;

#pragma unroll
        for (int ks = 0; ks < BK; ks += 16) {
            int acolB = (ks + a_c8) * 2;
            int bcolB = (ks + b_c8) * 2;
            uint32_t bh[4][4];
#pragma unroll
            for (int g = 0; g < 4; g++) {
                uint32_t ro = (uint32_t)((wn * 64 + g * 16 + b_r) * ROWB) + bcolB;
                ldsm_x4(base + B_OFF + ro, bh[g]);
            }
#pragma unroll
            for (int mi = 0; mi < 4; mi++) {
                uint32_t ah[4];
                uint32_t ro = (uint32_t)((wm * 64 + mi * 16 + a_r) * ROWB) + acolB;
                ldsm_x4(base + ro, ah);
#pragma unroll
                for (int g = 0; g < 4; g++) {
                    mma16816(acc[mi][2*g],   ah, bh[g][0], bh[g][1]);
                    mma16816(acc[mi][2*g+1], ah, bh[g][2], bh[g][3]);
                }
            }
        }
    }

#pragma unroll
    for (int mi = 0; mi < 4; mi++) {
#pragma unroll
        for (int j = 0; j < 8; j++) {
            int r0 = bm + wm * 64 + mi * 16 + (lane >> 2);
            int c0 = bn + wn * 64 + j * 8 + 2 * (lane & 3);
            float b0 = 0.f, b1 = 0.f;
            if (bias) { b0 = bias[c0]; b1 = bias[c0 + 1]; }
            float2 v0 = make_float2(acc[mi][j][0] + b0, acc[mi][j][1] + b1);
            float2 v1 = make_float2(acc[mi][j][2] + b0, acc[mi][j][3] + b1);
            *(float2*)(C + (size_t)r0 * N + c0) = v0;
            *(float2*)(C + (size_t)(r0 + 8) * N + c0) = v1;
        }
    }
}

// ======================= kernel: per-head RMSNorm + RoPE ====================
__global__ void qk_rope_kernel(const int* __restrict__ positions,
                               const float* __restrict__ qw,
                               const float* __restrict__ kw) {
    int t = blockIdx.x;
    int head = blockIdx.y;
    int i = threadIdx.x;   // 0..127
    float v = g_qkv[(size_t)t * QKVN_ + head * HD_ + i];

    if (head >= NH_ + NKV_) {   // v heads: single fp16 [KV,T,D]
        size_t idx = ((size_t)(head - NH_ - NKV_) * T_ + t) * HD_ + i;
        g_v[idx] = __float2half_rn(v);
        return;
    }

    float ss = v * v;
    for (int off = 16; off; off >>= 1)
        ss += __shfl_xor_sync(0xffffffffu, ss, off);
    __shared__ float wr[4];
    __shared__ float buf[HD_];
    int lane = i & 31, wid = i >> 5;
    if (lane == 0) wr[wid] = ss;
    __syncthreads();
    float tot = wr[0] + wr[1] + wr[2] + wr[3];
    float inv = rsqrtf(tot / (float)HD_ + 1e-6f);
    const float* w = (head < NH_) ? qw : kw;
    float nv = v * inv * w[i];
    buf[i] = nv;
    __syncthreads();

    int fi = i & 63;
    float invf = 1.0f / powf(10000.0f, (float)fi * (1.0f / 64.0f));
    float ang = (float)positions[t] * invf;
    float s, c;
    sincosf(ang, &s, &c);
    float other = buf[i ^ 64];
    float out = (i < 64) ? (nv * c - other * s) : (nv * c + other * s);

    if (head < NH_) {
        float sc = out * 0.08838834764831845f;   // fold in softmax scale
        size_t idx = ((size_t)head * T_ + t) * HD_ + i;
        __half h = __float2half_rn(sc);
        g_qh[idx] = h;
        g_ql[idx] = __float2half_rn(sc - __half2float(h));
    } else {
        size_t idx = ((size_t)(head - NH_) * T_ + t) * HD_ + i;
        g_k[idx] = __float2half_rn(out);
    }
}

// ======================= tensor-core flash attention ========================
// CTA: 64 q-rows x 1 head, 128 threads (4 warps x 16 rows). 2 CTAs/SM.
// 3-deep KV ring (Q area recycled). ONE sync per iter. Diagonal subtile
// skip (bit-exact). Numerics == R13.
#define ASTR 272                    // smem row stride bytes (136 fp16)
#define AQROWS 64
#define AQSZ (AQROWS * ASTR)        // 17408: one Q array (64 rows)
#define AKSZ (64 * ASTR)            // 17408: one K or V array (64 rows)
#define ASTAGE (2 * AKSZ)           // 34816: K,V  (== 2*AQSZ region size)
#define ATT_SMEM (2 * AQSZ + 2 * ASTAGE)   // 104448 -> 2 CTAs/SM

__device__ __forceinline__ uint32_t kv_region(uint32_t sb, int chunk) {
    int r = chunk % 3;
    return (r == 2) ? sb : sb + 2 * AQSZ + (uint32_t)r * ASTAGE;
}

__device__ __forceinline__ void attn_load_kv(
    uint32_t base,
    const __half* K, const __half* V,
    int kt0, int tid)
{
#pragma unroll
    for (int ii = 0; ii < 16; ii++) {
        int s = tid + ii * 128;
        int arr = s >> 10;          // 0=K 1=V
        int r = (s >> 4) & 63;
        int c = s & 15;
        const __half* src = (arr ? V : K) + (size_t)(kt0 + r) * HD_ + c * 8;
        uint32_t dst = base + arr * AKSZ + r * ASTR + c * 16;
        asm volatile("cp.async.cg.shared.global [%0], [%1], 16;"
                     :: "r"(dst), "l"(src));
    }
    asm volatile("cp.async.commit_group;" ::: "memory");
}

__global__ void __launch_bounds__(128, 2) attn_mma_kernel() {
    extern __shared__ char smc[];
    uint32_t sb = smem_to_u32(smc);
    int qb = (T_ / 64 - 1) - blockIdx.x;   // reversed: big workloads first
    int h  = blockIdx.y;
    int kvh = h >> 2;
    int tid = threadIdx.x, lane = tid & 31, wid = tid >> 5;

    const __half* Qhg = g_qh + ((size_t)h * T_ + qb * 64) * HD_;
    const __half* Qlg = g_ql + ((size_t)h * T_ + qb * 64) * HD_;
    const __half* Kg  = g_k  + (size_t)kvh * T_ * HD_;
    const __half* Vg  = g_v  + (size_t)kvh * T_ * HD_;

    // Q load (hi + lo): group 0
#pragma unroll
    for (int ii = 0; ii < 16; ii++) {
        int s = tid + ii * 128;
        int arr = s >> 10;              // 0 = hi, 1 = lo
        int r = (s >> 4) & 63;
        int c = s & 15;
        const __half* src = (arr ? Qlg : Qhg) + (size_t)r * HD_ + c * 8;
        uint32_t dst = sb + arr * AQSZ + r * ASTR + c * 16;
        asm volatile("cp.async.cg.shared.global [%0], [%1], 16;"
                     :: "r"(dst), "l"(src));
    }
    asm volatile("cp.async.commit_group;" ::: "memory");

    int nkt = qb + 1;
    attn_load_kv(kv_region(sb, 0), Kg, Vg, 0, tid);          // group 1
    if (nkt > 1) attn_load_kv(kv_region(sb, 1), Kg, Vg, 64, tid);  // group 2
    else         asm volatile("cp.async.commit_group;" ::: "memory");

    asm volatile("cp.async.wait_group 2;" ::: "memory");     // Q done
    __syncthreads();

    // extract Q fragments to registers (Q smem dead afterwards)
    int a_r = lane & 15, a_c8 = (lane >> 4) << 3;
    uint32_t qhf[8][4], qlf[8][4];
    {
        uint32_t qrow = (uint32_t)((wid * 16 + a_r) * ASTR);
#pragma unroll
        for (int j = 0; j < 8; j++) {
            uint32_t co = (uint32_t)((j * 16 + a_c8) * 2);
            ldsm_x4(sb + qrow + co, qhf[j]);
            ldsm_x4(sb + AQSZ + qrow + co, qlf[j]);
        }
    }
    __syncthreads();   // all warps done extracting before Q area is recycled

    float o[16][4];
#pragma unroll
    for (int j = 0; j < 16; j++)
#pragma unroll
        for (int c = 0; c < 4; c++) o[j][c] = 0.f;
    float mA = -1e30f, mB = -1e30f, lA = 0.f, lB = 0.f;

    int b_r = (lane & 7) + ((lane & 16) >> 1);   // K frag row map
    int b_c8 = (lane & 8);
    int v_r = (lane & 7) + 8 * ((lane >> 3) & 1);  // V trans frag row map
    int v_c8 = (lane >> 4) * 8;

    int wrow = qb * 64 + wid * 16;               // warp's first q row

    for (int kb = 0; kb < nkt; kb++) {
        asm volatile("cp.async.wait_group 1;" ::: "memory");
        __syncthreads();

        if (kb + 2 < nkt)
            attn_load_kv(kv_region(sb, kb + 2), Kg, Vg, (kb + 2) * 64, tid);
        else
            asm volatile("cp.async.commit_group;" ::: "memory");

        int kbase = kb * 64;
        bool active = (kbase <= wrow + 15);      // any unmasked element?
        uint32_t st = kv_region(sb, kb);

        if (active) {
            // subtile g/t valid iff kbase+16g <= wrow+15  (warp-uniform)
            int lim = (wrow + 15 - kbase) >> 4;  // >= 0 here; >=3 off-diagonal

            // ---- S = Q K^T (Q split x2, K single; skip masked subtiles) ----
            float s[8][4];
#pragma unroll
            for (int t = 0; t < 8; t++)
#pragma unroll
                for (int c = 0; c < 4; c++) s[t][c] = 0.f;

#pragma unroll
            for (int j = 0; j < 8; j++) {        // k16 over D
                uint32_t colB = (uint32_t)((j * 16 + b_c8) * 2);
#pragma unroll
                for (int g = 0; g < 4; g++) {    // n16 over 64 tokens
                    if (g <= lim) {
                        uint32_t kh[4];
                        uint32_t ro = st + (uint32_t)((g * 16 + b_r) * ASTR) + colB;
                        ldsm_x4(ro, kh);
                        mma16816(s[2*g],   qhf[j], kh[0], kh[1]);
                        mma16816(s[2*g],   qlf[j], kh[0], kh[1]);
                        mma16816(s[2*g+1], qhf[j], kh[2], kh[3]);
                        mma16816(s[2*g+1], qlf[j], kh[2], kh[3]);
                    }
                }
            }

            // ---- causal mask (diagonal tiles only) ----
            if (kbase + 63 > wrow) {
                int rA = wrow + (lane >> 2), rB = rA + 8;
#pragma unroll
                for (int t = 0; t < 8; t++) {
                    int c0 = kbase + t * 8 + 2 * (lane & 3);
                    if (c0     > rA) s[t][0] = -1e30f;
                    if (c0 + 1 > rA) s[t][1] = -1e30f;
                    if (c0     > rB) s[t][2] = -1e30f;
                    if (c0 + 1 > rB) s[t][3] = -1e30f;
                }
            }

            // ---- online softmax ----
            float rmA = -1e30f, rmB = -1e30f;
#pragma unroll
            for (int t = 0; t < 8; t++) {
                rmA = fmaxf(rmA, fmaxf(s[t][0], s[t][1]));
                rmB = fmaxf(rmB, fmaxf(s[t][2], s[t][3]));
            }
            rmA = fmaxf(rmA, __shfl_xor_sync(0xffffffffu, rmA, 1));
            rmA = fmaxf(rmA, __shfl_xor_sync(0xffffffffu, rmA, 2));
            rmB = fmaxf(rmB, __shfl_xor_sync(0xffffffffu, rmB, 1));
            rmB = fmaxf(rmB, __shfl_xor_sync(0xffffffffu, rmB, 2));
            float mnA = fmaxf(mA, rmA), mnB = fmaxf(mB, rmB);
            float aA = __expf(mA - mnA), aB = __expf(mB - mnB);
            mA = mnA; mB = mnB;

            float rsA = 0.f, rsB = 0.f;
#pragma unroll
            for (int t = 0; t < 8; t++) {
                s[t][0] = __expf(s[t][0] - mnA);
                s[t][1] = __expf(s[t][1] - mnA);
                s[t][2] = __expf(s[t][2] - mnB);
                s[t][3] = __expf(s[t][3] - mnB);
                rsA += s[t][0] + s[t][1];
                rsB += s[t][2] + s[t][3];
            }
            rsA += __shfl_xor_sync(0xffffffffu, rsA, 1);
            rsA += __shfl_xor_sync(0xffffffffu, rsA, 2);
            rsB += __shfl_xor_sync(0xffffffffu, rsB, 1);
            rsB += __shfl_xor_sync(0xffffffffu, rsB, 2);
            lA = lA * aA + rsA;
            lB = lB * aB + rsB;
#pragma unroll
            for (int j = 0; j < 16; j++) {
                o[j][0] *= aA; o[j][1] *= aA;
                o[j][2] *= aB; o[j][3] *= aB;
            }

            // ---- O += P V (P split x2, V single; skip all-zero P tiles) ----
#pragma unroll
            for (int t = 0; t < 4; t++) {        // k16 over 64 tokens
                if (t <= lim) {
                    uint32_t pah[4], pal[4];
                    split2h(s[2*t][0],   s[2*t][1],   pah[0], pal[0]);
                    split2h(s[2*t][2],   s[2*t][3],   pah[1], pal[1]);
                    split2h(s[2*t+1][0], s[2*t+1][1], pah[2], pal[2]);
                    split2h(s[2*t+1][2], s[2*t+1][3], pah[3], pal[3]);
                    uint32_t vrow = st + AKSZ
                                  + (uint32_t)((t * 16 + v_r) * ASTR);
#pragma unroll
                    for (int g = 0; g < 8; g++) {    // n16 over D
                        uint32_t vh[4];
                        uint32_t vo = vrow + (uint32_t)((g * 16 + v_c8) * 2);
                        ldsm_x4_trans(vo, vh);
                        mma16816(o[2*g],   pah, vh[0], vh[1]);
                        mma16816(o[2*g],   pal, vh[0], vh[1]);
                        mma16816(o[2*g+1], pah, vh[2], vh[3]);
                        mma16816(o[2*g+1], pal, vh[2], vh[3]);
                    }
                }
            }
        }
    }

    // ---- epilogue: normalize, write single fp16 ----
    float ilA = 1.f / lA, ilB = 1.f / lB;
    int rowA = wrow + (lane >> 2);
#pragma unroll
    for (int j = 0; j < 16; j++) {
        int col = h * HD_ + j * 8 + 2 * (lane & 3);
        *(uint32_t*)(g_att + (size_t)rowA * HS_ + col) =
            packh(o[j][0] * ilA, o[j][1] * ilA);
        *(uint32_t*)(g_att + (size_t)(rowA + 8) * HS_ + col) =
            packh(o[j][2] * ilB, o[j][3] * ilB);
    }
}

// ======================= launcher ===========================================
extern "C" void kernel_launch(void* const* d_in, const int* in_sizes, int n_in,
                              void* d_out, int out_size) {
    const int*   positions = (const int*)d_in[0];
    const float* hidden    = (const float*)d_in[1];
    const float* ln_w      = (const float*)d_in[2];
    const float* qkv_w     = (const float*)d_in[3];
    const float* qkv_b     = (const float*)d_in[4];
    const float* qn_w      = (const float*)d_in[5];
    const float* kn_w      = (const float*)d_in[6];
    const float* o_w       = (const float*)d_in[7];
    float* out = (float*)d_out;

    void* p;
    cudaGetSymbolAddress(&p, g_xn);   __half* xn  = (__half*)p;
    cudaGetSymbolAddress(&p, g_wq);   __half* wq  = (__half*)p;
    cudaGetSymbolAddress(&p, g_wo);   __half* wo  = (__half*)p;
    cudaGetSymbolAddress(&p, g_att);  __half* att = (__half*)p;
    cudaGetSymbolAddress(&p, g_qkv);  float* qkv = (float*)p;

    // 1) RMSNorm(hidden) -> fp16, with qkv_w conversion riding along
    rmsnorm_cvt_kernel<<<T_ + 256, 256>>>(hidden, ln_w, qkv_w);

    // 2) qkv = xn @ qkv_w^T + bias, with o_w conversion riding along
    cudaFuncSetAttribute(gemm_fp16_kernel,
                         cudaFuncAttributeMaxDynamicSharedMemorySize, GEMM_SMEM);
    gemm_fp16_kernel<<<dim3(QKVN_ / BN + 8, T_ / BM), 128, GEMM_SMEM>>>(
        xn, wq, qkv_b, qkv, QKVN_, HS_, QKVN_ / BN,
        o_w, wo, HS_ * HS_);

    // 3) q/k RMSNorm + RoPE (scale folded into q; q hi/lo split)
    qk_rope_kernel<<<dim3(T_, NH_ + 2 * NKV_), 128>>>(positions, qn_w, kn_w);

    // 4) causal attention (64-row CTAs, 2 CTA/SM, 3-deep ring, diag skip)
    cudaFuncSetAttribute(attn_mma_kernel,
                         cudaFuncAttributeMaxDynamicSharedMemorySize, ATT_SMEM);
    attn_mma_kernel<<<dim3(T_ / 64, NH_), 128, ATT_SMEM>>>();

    // 5) out = att @ o_w^T
    gemm_fp16_kernel<<<dim3(HS_ / BN, T_ / BM), 128, GEMM_SMEM>>>(
        att, wo, nullptr, out, HS_, HS_, HS_ / BN,
        nullptr, nullptr, 0);
}

// round 15
// speedup vs baseline: 1.0278x; 1.0278x over previous
#include <cuda_runtime.h>
#include <cuda_fp16.h>
#include <cstdint>
#include <math.h>

#define T_   2048
#define HS_  4096
#define NH_  32
#define NKV_ 8
#define HD_  128
#define QKVN_ ((NH_ + 2*NKV_)*HD_)   // 6144

// ======================= helpers ===========================================
__device__ __forceinline__ uint32_t smem_to_u32(const void* smem_ptr) {
    uint32_t addr;
    asm("{ .reg .u64 tmp; cvta.to.shared.u64 tmp, %1; cvt.u32.u64 %0, tmp; }"
        : "=r"(addr) : "l"(smem_ptr));
    return addr;
}
__device__ __forceinline__ void ldsm_x4(uint32_t addr, uint32_t* r) {
    asm volatile("ldmatrix.sync.aligned.m8n8.x4.shared.b16 {%0,%1,%2,%3}, [%4];"
        : "=r"(r[0]), "=r"(r[1]), "=r"(r[2]), "=r"(r[3]) : "r"(addr));
}
__device__ __forceinline__ void ldsm_x4_trans(uint32_t addr, uint32_t* r) {
    asm volatile("ldmatrix.sync.aligned.m8n8.x4.trans.shared.b16 {%0,%1,%2,%3}, [%4];"
        : "=r"(r[0]), "=r"(r[1]), "=r"(r[2]), "=r"(r[3]) : "r"(addr));
}
__device__ __forceinline__ void mma16816(float* d, const uint32_t* a,
                                         const uint32_t b0, const uint32_t b1) {
    asm volatile("mma.sync.aligned.m16n8k16.row.col.f32.f16.f16.f32 "
        "{%0,%1,%2,%3}, {%4,%5,%6,%7}, {%8,%9}, {%0,%1,%2,%3};"
        : "+f"(d[0]), "+f"(d[1]), "+f"(d[2]), "+f"(d[3])
        : "r"(a[0]), "r"(a[1]), "r"(a[2]), "r"(a[3]), "r"(b0), "r"(b1));
}
__device__ __forceinline__ uint32_t packh(float a, float b) {
    __half2 t = __floats2half2_rn(a, b);
    return *reinterpret_cast<uint32_t*>(&t);
}
__device__ __forceinline__ void split2h(float a, float b,
                                        uint32_t& hi, uint32_t& lo) {
    __half ha = __float2half_rn(a), hb = __float2half_rn(b);
    hi = packh(__half2float(ha), __half2float(hb));
    lo = packh(a - __half2float(ha), b - __half2float(hb));
}
__device__ __forceinline__ void cvt_f4(const float* __restrict__ src,
                                       __half* __restrict__ dst, int idx4) {
    float4 v = *(const float4*)(src + idx4 * 4);
    __half2* hp = (__half2*)(dst + idx4 * 4);
    hp[0] = __floats2half2_rn(v.x, v.y);
    hp[1] = __floats2half2_rn(v.z, v.w);
}

// ======================= scratch (device globals) ===========================
__device__ __align__(256) __half g_xn [T_*HS_];
__device__ __align__(256) __half g_wq [QKVN_*HS_];
__device__ __align__(256) __half g_wo [HS_*HS_];
__device__ __align__(256) __half g_att[T_*HS_];
__device__ float g_qkv[T_*QKVN_];
__device__ __align__(256) __half g_qh[NH_ *T_*HD_];
__device__ __align__(256) __half g_ql[NH_ *T_*HD_];
__device__ __align__(256) __half g_k [NKV_*T_*HD_];
__device__ __align__(256) __half g_v [NKV_*T_*HD_];

// ======================= kernel: RMSNorm(hidden) + qkv_w cvt riders =========
// blocks [0, T_): single-pass rmsnorm (row cached in registers).
// blocks [T_, T_+256): grid-stride fp32->fp16 convert of qkv_w.
__global__ void rmsnorm_cvt_kernel(const float* __restrict__ x,
                                   const float* __restrict__ w,
                                   const float* __restrict__ wq_src) {
    if (blockIdx.x >= T_) {
        int base = (blockIdx.x - T_) * 256 + threadIdx.x;
        int n4 = QKVN_ * HS_ / 4;
        for (int i = base; i < n4; i += 256 * 256)
            cvt_f4(wq_src, g_wq, i);
        return;
    }
    int row = blockIdx.x;
    const float* xr = x + (size_t)row * HS_;
    int tid = threadIdx.x;
    float vals[16];
    float ss = 0.f;
#pragma unroll
    for (int k = 0; k < 16; k++) {
        vals[k] = xr[tid + k * 256];
        ss += vals[k] * vals[k];
    }
    for (int off = 16; off; off >>= 1)
        ss += __shfl_xor_sync(0xffffffffu, ss, off);
    __shared__ float wr[8];
    int lane = tid & 31, wid = tid >> 5;
    if (lane == 0) wr[wid] = ss;
    __syncthreads();
    float tot = 0.f;
#pragma unroll
    for (int i = 0; i < 8; i++) tot += wr[i];
    float inv = rsqrtf(tot / (float)HS_ + 1e-6f);
#pragma unroll
    for (int k = 0; k < 16; k++) {
        int i = tid + k * 256;
        float v = vals[k] * inv * w[i];
        g_xn[(size_t)row * HS_ + i] = __float2half_rn(v);
    }
}

// ======================= fp16 GEMM: C = A*B^T (+bias) — R13 validated =======
// 128 threads, 4 warps (2x2), CTA 128x128, warp tile 64x64,
// BK=32, 4-stage ring, top-issued prefetch, ONE sync per iter, 2 CTAs/SM.
#define BM 128
#define BN 128
#define BK 32
#define ROWB 80                  // bytes per smem row: 40 fp16 (pad 32->40)
#define A_ARR (128 * ROWB)       // 10240 per array
#define B_OFF  A_ARR
#define STG  (2 * A_ARR)         // 20480 bytes per stage
#define NSTAGE 4
#define GEMM_SMEM (NSTAGE * STG) // 81920 -> 2 CTAs/SM

__device__ __forceinline__ void gemm_load_stage(
    uint32_t sb, int stage,
    const __half* __restrict__ A, const __half* __restrict__ B,
    int bm, int bn, int k0, int K, int tid)
{
    uint32_t base = sb + stage * STG;
#pragma unroll
    for (int ii = 0; ii < 8; ii++) {
        int s = tid + ii * 128;
        int arr = s >> 9;                // 0=A 1=B
        int r = (s >> 2) & 127, c = s & 3;
        const __half* srcb = arr ? B : A;
        int grow = (arr ? bn : bm) + r;
        const __half* src = srcb + (size_t)grow * K + k0 + c * 8;
        uint32_t dst = base + arr * A_ARR + r * ROWB + c * 16;
        asm volatile("cp.async.cg.shared.global [%0], [%1], 16;"
                     :: "r"(dst), "l"(src));
    }
    asm volatile("cp.async.commit_group;" ::: "memory");
}

__global__ void __launch_bounds__(128, 2)
gemm_fp16_kernel(const __half* __restrict__ A,
                 const __half* __restrict__ B,
                 const float* __restrict__ bias,
                 float* __restrict__ C, int N, int K)
{
    extern __shared__ char smem[];
    uint32_t sb = smem_to_u32(smem);
    int tid = threadIdx.x, lane = tid & 31, wid = tid >> 5;
    int wm = wid >> 1, wn = wid & 1;       // warp grid 2 x 2
    int bm = blockIdx.y * BM, bn = blockIdx.x * BN;
    int nk = K / BK;

    float acc[4][8][4];
#pragma unroll
    for (int i = 0; i < 4; i++)
#pragma unroll
        for (int j = 0; j < 8; j++)
#pragma unroll
            for (int c = 0; c < 4; c++) acc[i][j][c] = 0.f;

    gemm_load_stage(sb, 0, A, B, bm, bn, 0,      K, tid);
    gemm_load_stage(sb, 1, A, B, bm, bn, BK,     K, tid);
    gemm_load_stage(sb, 2, A, B, bm, bn, 2 * BK, K, tid);
    gemm_load_stage(sb, 3, A, B, bm, bn, 3 * BK, K, tid);

    int a_r = (lane & 15);
    int a_c8 = (lane >> 4) << 3;
    int b_r = (lane & 7) + ((lane & 16) >> 1);
    int b_c8 = (lane & 8);

    for (int it = 0; it < nk; it++) {
        asm volatile("cp.async.wait_group 2;" ::: "memory");
        __syncthreads();

        if (it >= 1) {
            if (it + 3 < nk)
                gemm_load_stage(sb, (it + 3) % NSTAGE, A, B, bm, bn,
                                (it + 3) * BK, K, tid);
            else
                asm volatile("cp.async.commit_group;" ::: "memory");
        }

        uint32_t base = sb + (it % NSTAGE) * STG;

#pragma unroll
        for (int ks = 0; ks < BK; ks += 16) {
            int acolB = (ks + a_c8) * 2;
            int bcolB = (ks + b_c8) * 2;
            uint32_t bh[4][4];
#pragma unroll
            for (int g = 0; g < 4; g++) {
                uint32_t ro = (uint32_t)((wn * 64 + g * 16 + b_r) * ROWB) + bcolB;
                ldsm_x4(base + B_OFF + ro, bh[g]);
            }
#pragma unroll
            for (int mi = 0; mi < 4; mi++) {
                uint32_t ah[4];
                uint32_t ro = (uint32_t)((wm * 64 + mi * 16 + a_r) * ROWB) + acolB;
                ldsm_x4(base + ro, ah);
#pragma unroll
                for (int g = 0; g < 4; g++) {
                    mma16816(acc[mi][2*g],   ah, bh[g][0], bh[g][1]);
                    mma16816(acc[mi][2*g+1], ah, bh[g][2], bh[g][3]);
                }
            }
        }
    }

#pragma unroll
    for (int mi = 0; mi < 4; mi++) {
#pragma unroll
        for (int j = 0; j < 8; j++) {
            int r0 = bm + wm * 64 + mi * 16 + (lane >> 2);
            int c0 = bn + wn * 64 + j * 8 + 2 * (lane & 3);
            float b0 = 0.f, b1 = 0.f;
            if (bias) { b0 = bias[c0]; b1 = bias[c0 + 1]; }
            float2 v0 = make_float2(acc[mi][j][0] + b0, acc[mi][j][1] + b1);
            float2 v1 = make_float2(acc[mi][j][2] + b0, acc[mi][j][3] + b1);
            *(float2*)(C + (size_t)r0 * N + c0) = v0;
            *(float2*)(C + (size_t)(r0 + 8) * N + c0) = v1;
        }
    }
}

// ======================= kernel: per-head RMSNorm + RoPE + o_w cvt riders ===
// plane blockIdx.y < 48: rope work. plane blockIdx.y == 48: o_w conversion
// riders (blockIdx.x < 512), overlapping DRAM cvt with MUFU-heavy rope.
__global__ void qk_rope_kernel(const int* __restrict__ positions,
                               const float* __restrict__ qw,
                               const float* __restrict__ kw,
                               const float* __restrict__ wo_src) {
    int head = blockIdx.y;
    if (head >= NH_ + 2 * NKV_) {
        if (blockIdx.x < 512) {
            int base = blockIdx.x * 128 + threadIdx.x;   // 65536 threads
            int n4 = HS_ * HS_ / 4;
            for (int i = base; i < n4; i += 512 * 128)
                cvt_f4(wo_src, g_wo, i);
        }
        return;
    }
    int t = blockIdx.x;
    int i = threadIdx.x;   // 0..127
    float v = g_qkv[(size_t)t * QKVN_ + head * HD_ + i];

    if (head >= NH_ + NKV_) {   // v heads: single fp16 [KV,T,D]
        size_t idx = ((size_t)(head - NH_ - NKV_) * T_ + t) * HD_ + i;
        g_v[idx] = __float2half_rn(v);
        return;
    }

    float ss = v * v;
    for (int off = 16; off; off >>= 1)
        ss += __shfl_xor_sync(0xffffffffu, ss, off);
    __shared__ float wr[4];
    __shared__ float buf[HD_];
    int lane = i & 31, wid = i >> 5;
    if (lane == 0) wr[wid] = ss;
    __syncthreads();
    float tot = wr[0] + wr[1] + wr[2] + wr[3];
    float inv = rsqrtf(tot / (float)HD_ + 1e-6f);
    const float* w = (head < NH_) ? qw : kw;
    float nv = v * inv * w[i];
    buf[i] = nv;
    __syncthreads();

    int fi = i & 63;
    float invf = 1.0f / powf(10000.0f, (float)fi * (1.0f / 64.0f));
    float ang = (float)positions[t] * invf;
    float s, c;
    sincosf(ang, &s, &c);
    float other = buf[i ^ 64];
    float out = (i < 64) ? (nv * c - other * s) : (nv * c + other * s);

    if (head < NH_) {
        float sc = out * 0.08838834764831845f;   // fold in softmax scale
        size_t idx = ((size_t)head * T_ + t) * HD_ + i;
        __half h = __float2half_rn(sc);
        g_qh[idx] = h;
        g_ql[idx] = __float2half_rn(sc - __half2float(h));
    } else {
        size_t idx = ((size_t)(head - NH_) * T_ + t) * HD_ + i;
        g_k[idx] = __float2half_rn(out);
    }
}

// ======================= tensor-core flash attention — R13 validated ========
// CTA: 64 q-rows x 1 head, 128 threads (4 warps x 16 rows). 2 CTAs/SM.
// 3-deep KV ring (Q area recycled). ONE sync per iteration.
#define ASTR 272                    // smem row stride bytes (136 fp16)
#define AQROWS 64
#define AQSZ (AQROWS * ASTR)        // 17408: one Q array (64 rows)
#define AKSZ (64 * ASTR)            // 17408: one K or V array (64 rows)
#define ASTAGE (2 * AKSZ)           // 34816: K,V  (== 2*AQSZ region size)
#define ATT_SMEM (2 * AQSZ + 2 * ASTAGE)   // 104448 -> 2 CTAs/SM

__device__ __forceinline__ uint32_t kv_region(uint32_t sb, int chunk) {
    int r = chunk % 3;
    return (r == 2) ? sb : sb + 2 * AQSZ + (uint32_t)r * ASTAGE;
}

__device__ __forceinline__ void attn_load_kv(
    uint32_t base,
    const __half* K, const __half* V,
    int kt0, int tid)
{
#pragma unroll
    for (int ii = 0; ii < 16; ii++) {
        int s = tid + ii * 128;
        int arr = s >> 10;          // 0=K 1=V
        int r = (s >> 4) & 63;
        int c = s & 15;
        const __half* src = (arr ? V : K) + (size_t)(kt0 + r) * HD_ + c * 8;
        uint32_t dst = base + arr * AKSZ + r * ASTR + c * 16;
        asm volatile("cp.async.cg.shared.global [%0], [%1], 16;"
                     :: "r"(dst), "l"(src));
    }
    asm volatile("cp.async.commit_group;" ::: "memory");
}

__global__ void __launch_bounds__(128, 2) attn_mma_kernel() {
    extern __shared__ char smc[];
    uint32_t sb = smem_to_u32(smc);
    int qb = (T_ / 64 - 1) - blockIdx.x;   // reversed: big workloads first
    int h  = blockIdx.y;
    int kvh = h >> 2;
    int tid = threadIdx.x, lane = tid & 31, wid = tid >> 5;

    const __half* Qhg = g_qh + ((size_t)h * T_ + qb * 64) * HD_;
    const __half* Qlg = g_ql + ((size_t)h * T_ + qb * 64) * HD_;
    const __half* Kg  = g_k  + (size_t)kvh * T_ * HD_;
    const __half* Vg  = g_v  + (size_t)kvh * T_ * HD_;

    // Q load (hi + lo): group 0
#pragma unroll
    for (int ii = 0; ii < 16; ii++) {
        int s = tid + ii * 128;
        int arr = s >> 10;              // 0 = hi, 1 = lo
        int r = (s >> 4) & 63;
        int c = s & 15;
        const __half* src = (arr ? Qlg : Qhg) + (size_t)r * HD_ + c * 8;
        uint32_t dst = sb + arr * AQSZ + r * ASTR + c * 16;
        asm volatile("cp.async.cg.shared.global [%0], [%1], 16;"
                     :: "r"(dst), "l"(src));
    }
    asm volatile("cp.async.commit_group;" ::: "memory");

    int nkt = qb + 1;
    attn_load_kv(kv_region(sb, 0), Kg, Vg, 0, tid);          // group 1
    if (nkt > 1) attn_load_kv(kv_region(sb, 1), Kg, Vg, 64, tid);  // group 2
    else         asm volatile("cp.async.commit_group;" ::: "memory");

    asm volatile("cp.async.wait_group 2;" ::: "memory");     // Q done
    __syncthreads();

    // extract Q fragments to registers (Q smem dead afterwards)
    int a_r = lane & 15, a_c8 = (lane >> 4) << 3;
    uint32_t qhf[8][4], qlf[8][4];
    {
        uint32_t qrow = (uint32_t)((wid * 16 + a_r) * ASTR);
#pragma unroll
        for (int j = 0; j < 8; j++) {
            uint32_t co = (uint32_t)((j * 16 + a_c8) * 2);
            ldsm_x4(sb + qrow + co, qhf[j]);
            ldsm_x4(sb + AQSZ + qrow + co, qlf[j]);
        }
    }
    __syncthreads();   // all warps done extracting before Q area is recycled

    float o[16][4];
#pragma unroll
    for (int j = 0; j < 16; j++)
#pragma unroll
        for (int c = 0; c < 4; c++) o[j][c] = 0.f;
    float mA = -1e30f, mB = -1e30f, lA = 0.f, lB = 0.f;

    int b_r = (lane & 7) + ((lane & 16) >> 1);   // K frag row map
    int b_c8 = (lane & 8);
    int v_r = (lane & 7) + 8 * ((lane >> 3) & 1);  // V trans frag row map
    int v_c8 = (lane >> 4) * 8;

    int wrow = qb * 64 + wid * 16;               // warp's first q row

    for (int kb = 0; kb < nkt; kb++) {
        asm volatile("cp.async.wait_group 1;" ::: "memory");
        __syncthreads();

        if (kb + 2 < nkt)
            attn_load_kv(kv_region(sb, kb + 2), Kg, Vg, (kb + 2) * 64, tid);
        else
            asm volatile("cp.async.commit_group;" ::: "memory");

        int kbase = kb * 64;
        bool active = (kbase <= wrow + 15);      // any unmasked element?
        uint32_t st = kv_region(sb, kb);

        if (active) {
            // ---- S = Q K^T (Q split x2, K single) ----
            float s[8][4];
#pragma unroll
            for (int t = 0; t < 8; t++)
#pragma unroll
                for (int c = 0; c < 4; c++) s[t][c] = 0.f;

#pragma unroll
            for (int j = 0; j < 8; j++) {        // k16 over D
                uint32_t colB = (uint32_t)((j * 16 + b_c8) * 2);
#pragma unroll
                for (int g = 0; g < 4; g++) {    // n16 over 64 tokens
                    uint32_t kh[4];
                    uint32_t ro = st + (uint32_t)((g * 16 + b_r) * ASTR) + colB;
                    ldsm_x4(ro, kh);
                    mma16816(s[2*g],   qhf[j], kh[0], kh[1]);
                    mma16816(s[2*g],   qlf[j], kh[0], kh[1]);
                    mma16816(s[2*g+1], qhf[j], kh[2], kh[3]);
                    mma16816(s[2*g+1], qlf[j], kh[2], kh[3]);
                }
            }

            // ---- causal mask (diagonal tiles only) ----
            if (kbase + 63 > wrow) {
                int rA = wrow + (lane >> 2), rB = rA + 8;
#pragma unroll
                for (int t = 0; t < 8; t++) {
                    int c0 = kbase + t * 8 + 2 * (lane & 3);
                    if (c0     > rA) s[t][0] = -1e30f;
                    if (c0 + 1 > rA) s[t][1] = -1e30f;
                    if (c0     > rB) s[t][2] = -1e30f;
                    if (c0 + 1 > rB) s[t][3] = -1e30f;
                }
            }

            // ---- online softmax ----
            float rmA = -1e30f, rmB = -1e30f;
#pragma unroll
            for (int t = 0; t < 8; t++) {
                rmA = fmaxf(rmA, fmaxf(s[t][0], s[t][1]));
                rmB = fmaxf(rmB, fmaxf(s[t][2], s[t][3]));
            }
            rmA = fmaxf(rmA, __shfl_xor_sync(0xffffffffu, rmA, 1));
            rmA = fmaxf(rmA, __shfl_xor_sync(0xffffffffu, rmA, 2));
            rmB = fmaxf(rmB, __shfl_xor_sync(0xffffffffu, rmB, 1));
            rmB = fmaxf(rmB, __shfl_xor_sync(0xffffffffu, rmB, 2));
            float mnA = fmaxf(mA, rmA), mnB = fmaxf(mB, rmB);
            float aA = __expf(mA - mnA), aB = __expf(mB - mnB);
            mA = mnA; mB = mnB;

            float rsA = 0.f, rsB = 0.f;
#pragma unroll
            for (int t = 0; t < 8; t++) {
                s[t][0] = __expf(s[t][0] - mnA);
                s[t][1] = __expf(s[t][1] - mnA);
                s[t][2] = __expf(s[t][2] - mnB);
                s[t][3] = __expf(s[t][3] - mnB);
                rsA += s[t][0] + s[t][1];
                rsB += s[t][2] + s[t][3];
            }
            rsA += __shfl_xor_sync(0xffffffffu, rsA, 1);
            rsA += __shfl_xor_sync(0xffffffffu, rsA, 2);
            rsB += __shfl_xor_sync(0xffffffffu, rsB, 1);
            rsB += __shfl_xor_sync(0xffffffffu, rsB, 2);
            lA = lA * aA + rsA;
            lB = lB * aB + rsB;
#pragma unroll
            for (int j = 0; j < 16; j++) {
                o[j][0] *= aA; o[j][1] *= aA;
                o[j][2] *= aB; o[j][3] *= aB;
            }

            // ---- O += P V (P split x2, V single) ----
#pragma unroll
            for (int t = 0; t < 4; t++) {        // k16 over 64 tokens
                uint32_t pah[4], pal[4];
                split2h(s[2*t][0],   s[2*t][1],   pah[0], pal[0]);
                split2h(s[2*t][2],   s[2*t][3],   pah[1], pal[1]);
                split2h(s[2*t+1][0], s[2*t+1][1], pah[2], pal[2]);
                split2h(s[2*t+1][2], s[2*t+1][3], pah[3], pal[3]);
                uint32_t vrow = st + AKSZ
                              + (uint32_t)((t * 16 + v_r) * ASTR);
#pragma unroll
                for (int g = 0; g < 8; g++) {    // n16 over D
                    uint32_t vh[4];
                    uint32_t vo = vrow + (uint32_t)((g * 16 + v_c8) * 2);
                    ldsm_x4_trans(vo, vh);
                    mma16816(o[2*g],   pah, vh[0], vh[1]);
                    mma16816(o[2*g],   pal, vh[0], vh[1]);
                    mma16816(o[2*g+1], pah, vh[2], vh[3]);
                    mma16816(o[2*g+1], pal, vh[2], vh[3]);
                }
            }
        }
    }

    // ---- epilogue: normalize, write single fp16 ----
    float ilA = 1.f / lA, ilB = 1.f / lB;
    int rowA = wrow + (lane >> 2);
#pragma unroll
    for (int j = 0; j < 16; j++) {
        int col = h * HD_ + j * 8 + 2 * (lane & 3);
        *(uint32_t*)(g_att + (size_t)rowA * HS_ + col) =
            packh(o[j][0] * ilA, o[j][1] * ilA);
        *(uint32_t*)(g_att + (size_t)(rowA + 8) * HS_ + col) =
            packh(o[j][2] * ilB, o[j][3] * ilB);
    }
}

// ======================= launcher ===========================================
extern "C" void kernel_launch(void* const* d_in, const int* in_sizes, int n_in,
                              void* d_out, int out_size) {
    const int*   positions = (const int*)d_in[0];
    const float* hidden    = (const float*)d_in[1];
    const float* ln_w      = (const float*)d_in[2];
    const float* qkv_w     = (const float*)d_in[3];
    const float* qkv_b     = (const float*)d_in[4];
    const float* qn_w      = (const float*)d_in[5];
    const float* kn_w      = (const float*)d_in[6];
    const float* o_w       = (const float*)d_in[7];
    float* out = (float*)d_out;

    void* p;
    cudaGetSymbolAddress(&p, g_xn);   __half* xn  = (__half*)p;
    cudaGetSymbolAddress(&p, g_wq);   __half* wq  = (__half*)p;
    cudaGetSymbolAddress(&p, g_wo);   __half* wo  = (__half*)p;
    cudaGetSymbolAddress(&p, g_att);  __half* att = (__half*)p;
    cudaGetSymbolAddress(&p, g_qkv);  float* qkv = (float*)p;

    // 1) RMSNorm(hidden) -> fp16 (single-pass), qkv_w cvt rides along
    rmsnorm_cvt_kernel<<<T_ + 256, 256>>>(hidden, ln_w, qkv_w);

    // 2) qkv = xn @ qkv_w^T + bias   (R13 GEMM, no riders)
    cudaFuncSetAttribute(gemm_fp16_kernel,
                         cudaFuncAttributeMaxDynamicSharedMemorySize, GEMM_SMEM);
    gemm_fp16_kernel<<<dim3(QKVN_ / BN, T_ / BM), 128, GEMM_SMEM>>>(
        xn, wq, qkv_b, qkv, QKVN_, HS_);

    // 3) q/k RMSNorm + RoPE; o_w cvt rides in plane y==48
    qk_rope_kernel<<<dim3(T_, NH_ + 2 * NKV_ + 1), 128>>>(
        positions, qn_w, kn_w, o_w);

    // 4) causal attention (exact R13)
    cudaFuncSetAttribute(attn_mma_kernel,
                         cudaFuncAttributeMaxDynamicSharedMemorySize, ATT_SMEM);
    attn_mma_kernel<<<dim3(T_ / 64, NH_), 128, ATT_SMEM>>>();

    // 5) out = att @ o_w^T
    gemm_fp16_kernel<<<dim3(HS_ / BN, T_ / BM), 128, GEMM_SMEM>>>(
        att, wo, nullptr, out, HS_, HS_);
}

// round 16
// speedup vs baseline: 1.0809x; 1.0517x over previous
#include <cuda_runtime.h>
#include <cuda_fp16.h>
#include <cstdint>
#include <math.h>

#define T_   2048
#define HS_  4096
#define NH_  32
#define NKV_ 8
#define HD_  128
#define QKVN_ ((NH_ + 2*NKV_)*HD_)   // 6144

// ======================= helpers ===========================================
__device__ __forceinline__ uint32_t smem_to_u32(const void* smem_ptr) {
    uint32_t addr;
    asm("{ .reg .u64 tmp; cvta.to.shared.u64 tmp, %1; cvt.u32.u64 %0, tmp; }"
        : "=r"(addr) : "l"(smem_ptr));
    return addr;
}
__device__ __forceinline__ void ldsm_x4(uint32_t addr, uint32_t* r) {
    asm volatile("ldmatrix.sync.aligned.m8n8.x4.shared.b16 {%0,%1,%2,%3}, [%4];"
        : "=r"(r[0]), "=r"(r[1]), "=r"(r[2]), "=r"(r[3]) : "r"(addr));
}
__device__ __forceinline__ void ldsm_x4_trans(uint32_t addr, uint32_t* r) {
    asm volatile("ldmatrix.sync.aligned.m8n8.x4.trans.shared.b16 {%0,%1,%2,%3}, [%4];"
        : "=r"(r[0]), "=r"(r[1]), "=r"(r[2]), "=r"(r[3]) : "r"(addr));
}
__device__ __forceinline__ void mma16816(float* d, const uint32_t* a,
                                         const uint32_t b0, const uint32_t b1) {
    asm volatile("mma.sync.aligned.m16n8k16.row.col.f32.f16.f16.f32 "
        "{%0,%1,%2,%3}, {%4,%5,%6,%7}, {%8,%9}, {%0,%1,%2,%3};"
        : "+f"(d[0]), "+f"(d[1]), "+f"(d[2]), "+f"(d[3])
        : "r"(a[0]), "r"(a[1]), "r"(a[2]), "r"(a[3]), "r"(b0), "r"(b1));
}
__device__ __forceinline__ uint32_t packh(float a, float b) {
    __half2 t = __floats2half2_rn(a, b);
    return *reinterpret_cast<uint32_t*>(&t);
}
__device__ __forceinline__ void split2h(float a, float b,
                                        uint32_t& hi, uint32_t& lo) {
    __half ha = __float2half_rn(a), hb = __float2half_rn(b);
    hi = packh(__half2float(ha), __half2float(hb));
    lo = packh(a - __half2float(ha), b - __half2float(hb));
}
__device__ __forceinline__ void cvt_f4(const float* __restrict__ src,
                                       __half* __restrict__ dst, int idx4) {
    float4 v = *(const float4*)(src + idx4 * 4);
    __half2* hp = (__half2*)(dst + idx4 * 4);
    hp[0] = __floats2half2_rn(v.x, v.y);
    hp[1] = __floats2half2_rn(v.z, v.w);
}

// ======================= scratch (device globals) ===========================
__device__ __align__(256) __half g_xn [T_*HS_];
__device__ __align__(256) __half g_wq [QKVN_*HS_];
__device__ __align__(256) __half g_wo [HS_*HS_];
__device__ __align__(256) __half g_att[T_*HS_];
__device__ float g_qkv[T_*QKVN_];
__device__ __align__(256) __half g_qh[NH_ *T_*HD_];
__device__ __align__(256) __half g_ql[NH_ *T_*HD_];
__device__ __align__(256) __half g_k [NKV_*T_*HD_];
__device__ __align__(256) __half g_v [NKV_*T_*HD_];

// ======================= kernel: RMSNorm(hidden) + qkv_w cvt riders =========
__global__ void rmsnorm_cvt_kernel(const float* __restrict__ x,
                                   const float* __restrict__ w,
                                   const float* __restrict__ wq_src) {
    if (blockIdx.x >= T_) {
        int base = (blockIdx.x - T_) * 256 + threadIdx.x;
        int n4 = QKVN_ * HS_ / 4;
        for (int i = base; i < n4; i += 256 * 256)
            cvt_f4(wq_src, g_wq, i);
        return;
    }
    int row = blockIdx.x;
    const float* xr = x + (size_t)row * HS_;
    int tid = threadIdx.x;
    float vals[16];
    float ss = 0.f;
#pragma unroll
    for (int k = 0; k < 16; k++) {
        vals[k] = xr[tid + k * 256];
        ss += vals[k] * vals[k];
    }
    for (int off = 16; off; off >>= 1)
        ss += __shfl_xor_sync(0xffffffffu, ss, off);
    __shared__ float wr[8];
    int lane = tid & 31, wid = tid >> 5;
    if (lane == 0) wr[wid] = ss;
    __syncthreads();
    float tot = 0.f;
#pragma unroll
    for (int i = 0; i < 8; i++) tot += wr[i];
    float inv = rsqrtf(tot / (float)HS_ + 1e-6f);
#pragma unroll
    for (int k = 0; k < 16; k++) {
        int i = tid + k * 256;
        float v = vals[k] * inv * w[i];
        g_xn[(size_t)row * HS_ + i] = __float2half_rn(v);
    }
}

// ======================= fp16 GEMM: C = A*B^T (+bias) — R13 validated =======
#define BM 128
#define BN 128
#define BK 32
#define ROWB 80                  // bytes per smem row: 40 fp16 (pad 32->40)
#define A_ARR (128 * ROWB)       // 10240 per array
#define B_OFF  A_ARR
#define STG  (2 * A_ARR)         // 20480 bytes per stage
#define NSTAGE 4
#define GEMM_SMEM (NSTAGE * STG) // 81920 -> 2 CTAs/SM

__device__ __forceinline__ void gemm_load_stage(
    uint32_t sb, int stage,
    const __half* __restrict__ A, const __half* __restrict__ B,
    int bm, int bn, int k0, int K, int tid)
{
    uint32_t base = sb + stage * STG;
#pragma unroll
    for (int ii = 0; ii < 8; ii++) {
        int s = tid + ii * 128;
        int arr = s >> 9;                // 0=A 1=B
        int r = (s >> 2) & 127, c = s & 3;
        const __half* srcb = arr ? B : A;
        int grow = (arr ? bn : bm) + r;
        const __half* src = srcb + (size_t)grow * K + k0 + c * 8;
        uint32_t dst = base + arr * A_ARR + r * ROWB + c * 16;
        asm volatile("cp.async.cg.shared.global [%0], [%1], 16;"
                     :: "r"(dst), "l"(src));
    }
    asm volatile("cp.async.commit_group;" ::: "memory");
}

__global__ void __launch_bounds__(128, 2)
gemm_fp16_kernel(const __half* __restrict__ A,
                 const __half* __restrict__ B,
                 const float* __restrict__ bias,
                 float* __restrict__ C, int N, int K)
{
    extern __shared__ char smem[];
    uint32_t sb = smem_to_u32(smem);
    int tid = threadIdx.x, lane = tid & 31, wid = tid >> 5;
    int wm = wid >> 1, wn = wid & 1;       // warp grid 2 x 2
    int bm = blockIdx.y * BM, bn = blockIdx.x * BN;
    int nk = K / BK;

    float acc[4][8][4];
#pragma unroll
    for (int i = 0; i < 4; i++)
#pragma unroll
        for (int j = 0; j < 8; j++)
#pragma unroll
            for (int c = 0; c < 4; c++) acc[i][j][c] = 0.f;

    gemm_load_stage(sb, 0, A, B, bm, bn, 0,      K, tid);
    gemm_load_stage(sb, 1, A, B, bm, bn, BK,     K, tid);
    gemm_load_stage(sb, 2, A, B, bm, bn, 2 * BK, K, tid);
    gemm_load_stage(sb, 3, A, B, bm, bn, 3 * BK, K, tid);

    int a_r = (lane & 15);
    int a_c8 = (lane >> 4) << 3;
    int b_r = (lane & 7) + ((lane & 16) >> 1);
    int b_c8 = (lane & 8);

    for (int it = 0; it < nk; it++) {
        asm volatile("cp.async.wait_group 2;" ::: "memory");
        __syncthreads();

        if (it >= 1) {
            if (it + 3 < nk)
                gemm_load_stage(sb, (it + 3) % NSTAGE, A, B, bm, bn,
                                (it + 3) * BK, K, tid);
            else
                asm volatile("cp.async.commit_group;" ::: "memory");
        }

        uint32_t base = sb + (it % NSTAGE) * STG;

#pragma unroll
        for (int ks = 0; ks < BK; ks += 16) {
            int acolB = (ks + a_c8) * 2;
            int bcolB = (ks + b_c8) * 2;
            uint32_t bh[4][4];
#pragma unroll
            for (int g = 0; g < 4; g++) {
                uint32_t ro = (uint32_t)((wn * 64 + g * 16 + b_r) * ROWB) + bcolB;
                ldsm_x4(base + B_OFF + ro, bh[g]);
            }
#pragma unroll
            for (int mi = 0; mi < 4; mi++) {
                uint32_t ah[4];
                uint32_t ro = (uint32_t)((wm * 64 + mi * 16 + a_r) * ROWB) + acolB;
                ldsm_x4(base + ro, ah);
#pragma unroll
                for (int g = 0; g < 4; g++) {
                    mma16816(acc[mi][2*g],   ah, bh[g][0], bh[g][1]);
                    mma16816(acc[mi][2*g+1], ah, bh[g][2], bh[g][3]);
                }
            }
        }
    }

#pragma unroll
    for (int mi = 0; mi < 4; mi++) {
#pragma unroll
        for (int j = 0; j < 8; j++) {
            int r0 = bm + wm * 64 + mi * 16 + (lane >> 2);
            int c0 = bn + wn * 64 + j * 8 + 2 * (lane & 3);
            float b0 = 0.f, b1 = 0.f;
            if (bias) { b0 = bias[c0]; b1 = bias[c0 + 1]; }
            float2 v0 = make_float2(acc[mi][j][0] + b0, acc[mi][j][1] + b1);
            float2 v1 = make_float2(acc[mi][j][2] + b0, acc[mi][j][3] + b1);
            *(float2*)(C + (size_t)r0 * N + c0) = v0;
            *(float2*)(C + (size_t)(r0 + 8) * N + c0) = v1;
        }
    }
}

// ======================= kernel: per-head RMSNorm + RoPE + o_w cvt riders ===
__global__ void qk_rope_kernel(const int* __restrict__ positions,
                               const float* __restrict__ qw,
                               const float* __restrict__ kw,
                               const float* __restrict__ wo_src) {
    int head = blockIdx.y;
    if (head >= NH_ + 2 * NKV_) {
        if (blockIdx.x < 512) {
            int base = blockIdx.x * 128 + threadIdx.x;   // 65536 threads
            int n4 = HS_ * HS_ / 4;
            for (int i = base; i < n4; i += 512 * 128)
                cvt_f4(wo_src, g_wo, i);
        }
        return;
    }
    int t = blockIdx.x;
    int i = threadIdx.x;   // 0..127
    float v = g_qkv[(size_t)t * QKVN_ + head * HD_ + i];

    if (head >= NH_ + NKV_) {   // v heads: single fp16 [KV,T,D]
        size_t idx = ((size_t)(head - NH_ - NKV_) * T_ + t) * HD_ + i;
        g_v[idx] = __float2half_rn(v);
        return;
    }

    float ss = v * v;
    for (int off = 16; off; off >>= 1)
        ss += __shfl_xor_sync(0xffffffffu, ss, off);
    __shared__ float wr[4];
    __shared__ float buf[HD_];
    int lane = i & 31, wid = i >> 5;
    if (lane == 0) wr[wid] = ss;
    __syncthreads();
    float tot = wr[0] + wr[1] + wr[2] + wr[3];
    float inv = rsqrtf(tot / (float)HD_ + 1e-6f);
    const float* w = (head < NH_) ? qw : kw;
    float nv = v * inv * w[i];
    buf[i] = nv;
    __syncthreads();

    int fi = i & 63;
    float invf = 1.0f / powf(10000.0f, (float)fi * (1.0f / 64.0f));
    float ang = (float)positions[t] * invf;
    float s, c;
    sincosf(ang, &s, &c);
    float other = buf[i ^ 64];
    float out = (i < 64) ? (nv * c - other * s) : (nv * c + other * s);

    if (head < NH_) {
        float sc = out * 0.08838834764831845f;   // fold in softmax scale
        size_t idx = ((size_t)head * T_ + t) * HD_ + i;
        __half h = __float2half_rn(sc);
        g_qh[idx] = h;
        g_ql[idx] = __float2half_rn(sc - __half2float(h));
    } else {
        size_t idx = ((size_t)(head - NH_) * T_ + t) * HD_ + i;
        g_k[idx] = __float2half_rn(out);
    }
}

// ======================= tensor-core flash attention ========================
// CTA: 64 q-rows x 1 head, 128 threads. 2 CTAs/SM. 3-deep KV ring.
// QK: Q split x2 (frozen — softmax input). PV: P SINGLE-pass fp16.
#define ASTR 272                    // smem row stride bytes (136 fp16)
#define AQROWS 64
#define AQSZ (AQROWS * ASTR)        // 17408: one Q array (64 rows)
#define AKSZ (64 * ASTR)            // 17408: one K or V array (64 rows)
#define ASTAGE (2 * AKSZ)           // 34816: K,V  (== 2*AQSZ region size)
#define ATT_SMEM (2 * AQSZ + 2 * ASTAGE)   // 104448 -> 2 CTAs/SM

__device__ __forceinline__ uint32_t kv_region(uint32_t sb, int chunk) {
    int r = chunk % 3;
    return (r == 2) ? sb : sb + 2 * AQSZ + (uint32_t)r * ASTAGE;
}

__device__ __forceinline__ void attn_load_kv(
    uint32_t base,
    const __half* K, const __half* V,
    int kt0, int tid)
{
#pragma unroll
    for (int ii = 0; ii < 16; ii++) {
        int s = tid + ii * 128;
        int arr = s >> 10;          // 0=K 1=V
        int r = (s >> 4) & 63;
        int c = s & 15;
        const __half* src = (arr ? V : K) + (size_t)(kt0 + r) * HD_ + c * 8;
        uint32_t dst = base + arr * AKSZ + r * ASTR + c * 16;
        asm volatile("cp.async.cg.shared.global [%0], [%1], 16;"
                     :: "r"(dst), "l"(src));
    }
    asm volatile("cp.async.commit_group;" ::: "memory");
}

__global__ void __launch_bounds__(128, 2) attn_mma_kernel() {
    extern __shared__ char smc[];
    uint32_t sb = smem_to_u32(smc);
    int qb = (T_ / 64 - 1) - blockIdx.x;   // reversed: big workloads first
    int h  = blockIdx.y;
    int kvh = h >> 2;
    int tid = threadIdx.x, lane = tid & 31, wid = tid >> 5;

    const __half* Qhg = g_qh + ((size_t)h * T_ + qb * 64) * HD_;
    const __half* Qlg = g_ql + ((size_t)h * T_ + qb * 64) * HD_;
    const __half* Kg  = g_k  + (size_t)kvh * T_ * HD_;
    const __half* Vg  = g_v  + (size_t)kvh * T_ * HD_;

    // Q load (hi + lo): group 0
#pragma unroll
    for (int ii = 0; ii < 16; ii++) {
        int s = tid + ii * 128;
        int arr = s >> 10;              // 0 = hi, 1 = lo
        int r = (s >> 4) & 63;
        int c = s & 15;
        const __half* src = (arr ? Qlg : Qhg) + (size_t)r * HD_ + c * 8;
        uint32_t dst = sb + arr * AQSZ + r * ASTR + c * 16;
        asm volatile("cp.async.cg.shared.global [%0], [%1], 16;"
                     :: "r"(dst), "l"(src));
    }
    asm volatile("cp.async.commit_group;" ::: "memory");

    int nkt = qb + 1;
    attn_load_kv(kv_region(sb, 0), Kg, Vg, 0, tid);          // group 1
    if (nkt > 1) attn_load_kv(kv_region(sb, 1), Kg, Vg, 64, tid);  // group 2
    else         asm volatile("cp.async.commit_group;" ::: "memory");

    asm volatile("cp.async.wait_group 2;" ::: "memory");     // Q done
    __syncthreads();

    // extract Q fragments to registers (Q smem dead afterwards)
    int a_r = lane & 15, a_c8 = (lane >> 4) << 3;
    uint32_t qhf[8][4], qlf[8][4];
    {
        uint32_t qrow = (uint32_t)((wid * 16 + a_r) * ASTR);
#pragma unroll
        for (int j = 0; j < 8; j++) {
            uint32_t co = (uint32_t)((j * 16 + a_c8) * 2);
            ldsm_x4(sb + qrow + co, qhf[j]);
            ldsm_x4(sb + AQSZ + qrow + co, qlf[j]);
        }
    }
    __syncthreads();   // all warps done extracting before Q area is recycled

    float o[16][4];
#pragma unroll
    for (int j = 0; j < 16; j++)
#pragma unroll
        for (int c = 0; c < 4; c++) o[j][c] = 0.f;
    float mA = -1e30f, mB = -1e30f, lA = 0.f, lB = 0.f;

    int b_r = (lane & 7) + ((lane & 16) >> 1);   // K frag row map
    int b_c8 = (lane & 8);
    int v_r = (lane & 7) + 8 * ((lane >> 3) & 1);  // V trans frag row map
    int v_c8 = (lane >> 4) * 8;

    int wrow = qb * 64 + wid * 16;               // warp's first q row

    for (int kb = 0; kb < nkt; kb++) {
        asm volatile("cp.async.wait_group 1;" ::: "memory");
        __syncthreads();

        if (kb + 2 < nkt)
            attn_load_kv(kv_region(sb, kb + 2), Kg, Vg, (kb + 2) * 64, tid);
        else
            asm volatile("cp.async.commit_group;" ::: "memory");

        int kbase = kb * 64;
        bool active = (kbase <= wrow + 15);      // any unmasked element?
        uint32_t st = kv_region(sb, kb);

        if (active) {
            // ---- S = Q K^T (Q split x2, K single) ----
            float s[8][4];
#pragma unroll
            for (int t = 0; t < 8; t++)
#pragma unroll
                for (int c = 0; c < 4; c++) s[t][c] = 0.f;

#pragma unroll
            for (int j = 0; j < 8; j++) {        // k16 over D
                uint32_t colB = (uint32_t)((j * 16 + b_c8) * 2);
#pragma unroll
                for (int g = 0; g < 4; g++) {    // n16 over 64 tokens
                    uint32_t kh[4];
                    uint32_t ro = st + (uint32_t)((g * 16 + b_r) * ASTR) + colB;
                    ldsm_x4(ro, kh);
                    mma16816(s[2*g],   qhf[j], kh[0], kh[1]);
                    mma16816(s[2*g],   qlf[j], kh[0], kh[1]);
                    mma16816(s[2*g+1], qhf[j], kh[2], kh[3]);
                    mma16816(s[2*g+1], qlf[j], kh[2], kh[3]);
                }
            }

            // ---- causal mask (diagonal tiles only) ----
            if (kbase + 63 > wrow) {
                int rA = wrow + (lane >> 2), rB = rA + 8;
#pragma unroll
                for (int t = 0; t < 8; t++) {
                    int c0 = kbase + t * 8 + 2 * (lane & 3);
                    if (c0     > rA) s[t][0] = -1e30f;
                    if (c0 + 1 > rA) s[t][1] = -1e30f;
                    if (c0     > rB) s[t][2] = -1e30f;
                    if (c0 + 1 > rB) s[t][3] = -1e30f;
                }
            }

            // ---- online softmax ----
            float rmA = -1e30f, rmB = -1e30f;
#pragma unroll
            for (int t = 0; t < 8; t++) {
                rmA = fmaxf(rmA, fmaxf(s[t][0], s[t][1]));
                rmB = fmaxf(rmB, fmaxf(s[t][2], s[t][3]));
            }
            rmA = fmaxf(rmA, __shfl_xor_sync(0xffffffffu, rmA, 1));
            rmA = fmaxf(rmA, __shfl_xor_sync(0xffffffffu, rmA, 2));
            rmB = fmaxf(rmB, __shfl_xor_sync(0xffffffffu, rmB, 1));
            rmB = fmaxf(rmB, __shfl_xor_sync(0xffffffffu, rmB, 2));
            float mnA = fmaxf(mA, rmA), mnB = fmaxf(mB, rmB);
            float aA = __expf(mA - mnA), aB = __expf(mB - mnB);
            mA = mnA; mB = mnB;

            float rsA = 0.f, rsB = 0.f;
#pragma unroll
            for (int t = 0; t < 8; t++) {
                s[t][0] = __expf(s[t][0] - mnA);
                s[t][1] = __expf(s[t][1] - mnA);
                s[t][2] = __expf(s[t][2] - mnB);
                s[t][3] = __expf(s[t][3] - mnB);
                rsA += s[t][0] + s[t][1];
                rsB += s[t][2] + s[t][3];
            }
            rsA += __shfl_xor_sync(0xffffffffu, rsA, 1);
            rsA += __shfl_xor_sync(0xffffffffu, rsA, 2);
            rsB += __shfl_xor_sync(0xffffffffu, rsB, 1);
            rsB += __shfl_xor_sync(0xffffffffu, rsB, 2);
            lA = lA * aA + rsA;
            lB = lB * aB + rsB;
#pragma unroll
            for (int j = 0; j < 16; j++) {
                o[j][0] *= aA; o[j][1] *= aA;
                o[j][2] *= aB; o[j][3] *= aB;
            }

            // ---- O += P V (P single-pass fp16, V single) ----
#pragma unroll
            for (int t = 0; t < 4; t++) {        // k16 over 64 tokens
                uint32_t pa[4];
                pa[0] = packh(s[2*t][0],   s[2*t][1]);
                pa[1] = packh(s[2*t][2],   s[2*t][3]);
                pa[2] = packh(s[2*t+1][0], s[2*t+1][1]);
                pa[3] = packh(s[2*t+1][2], s[2*t+1][3]);
                uint32_t vrow = st + AKSZ
                              + (uint32_t)((t * 16 + v_r) * ASTR);
#pragma unroll
                for (int g = 0; g < 8; g++) {    // n16 over D
                    uint32_t vh[4];
                    uint32_t vo = vrow + (uint32_t)((g * 16 + v_c8) * 2);
                    ldsm_x4_trans(vo, vh);
                    mma16816(o[2*g],   pa, vh[0], vh[1]);
                    mma16816(o[2*g+1], pa, vh[2], vh[3]);
                }
            }
        }
    }

    // ---- epilogue: normalize, write single fp16 ----
    float ilA = 1.f / lA, ilB = 1.f / lB;
    int rowA = wrow + (lane >> 2);
#pragma unroll
    for (int j = 0; j < 16; j++) {
        int col = h * HD_ + j * 8 + 2 * (lane & 3);
        *(uint32_t*)(g_att + (size_t)rowA * HS_ + col) =
            packh(o[j][0] * ilA, o[j][1] * ilA);
        *(uint32_t*)(g_att + (size_t)(rowA + 8) * HS_ + col) =
            packh(o[j][2] * ilB, o[j][3] * ilB);
    }
}

// ======================= launcher ===========================================
extern "C" void kernel_launch(void* const* d_in, const int* in_sizes, int n_in,
                              void* d_out, int out_size) {
    const int*   positions = (const int*)d_in[0];
    const float* hidden    = (const float*)d_in[1];
    const float* ln_w      = (const float*)d_in[2];
    const float* qkv_w     = (const float*)d_in[3];
    const float* qkv_b     = (const float*)d_in[4];
    const float* qn_w      = (const float*)d_in[5];
    const float* kn_w      = (const float*)d_in[6];
    const float* o_w       = (const float*)d_in[7];
    float* out = (float*)d_out;

    void* p;
    cudaGetSymbolAddress(&p, g_xn);   __half* xn  = (__half*)p;
    cudaGetSymbolAddress(&p, g_wq);   __half* wq  = (__half*)p;
    cudaGetSymbolAddress(&p, g_wo);   __half* wo  = (__half*)p;
    cudaGetSymbolAddress(&p, g_att);  __half* att = (__half*)p;
    cudaGetSymbolAddress(&p, g_qkv);  float* qkv = (float*)p;

    // 1) RMSNorm(hidden) -> fp16 (single-pass), qkv_w cvt rides along
    rmsnorm_cvt_kernel<<<T_ + 256, 256>>>(hidden, ln_w, qkv_w);

    // 2) qkv = xn @ qkv_w^T + bias
    cudaFuncSetAttribute(gemm_fp16_kernel,
                         cudaFuncAttributeMaxDynamicSharedMemorySize, GEMM_SMEM);
    gemm_fp16_kernel<<<dim3(QKVN_ / BN, T_ / BM), 128, GEMM_SMEM>>>(
        xn, wq, qkv_b, qkv, QKVN_, HS_);

    // 3) q/k RMSNorm + RoPE; o_w cvt rides in plane y==48
    qk_rope_kernel<<<dim3(T_, NH_ + 2 * NKV_ + 1), 128>>>(
        positions, qn_w, kn_w, o_w);

    // 4) causal attention (PV single-pass)
    cudaFuncSetAttribute(attn_mma_kernel,
                         cudaFuncAttributeMaxDynamicSharedMemorySize, ATT_SMEM);
    attn_mma_kernel<<<dim3(T_ / 64, NH_), 128, ATT_SMEM>>>();

    // 5) out = att @ o_w^T
    gemm_fp16_kernel<<<dim3(HS_ / BN, T_ / BM), 128, GEMM_SMEM>>>(
        att, wo, nullptr, out, HS_, HS_);
}